// round 12
// baseline (speedup 1.0000x reference)
#include <cuda_runtime.h>
#include <cuda_bf16.h>
#include <math_constants.h>

__device__ __forceinline__ float4 fmax4(float4 a, float4 b) {
    a.x = fmaxf(a.x, b.x);
    a.y = fmaxf(a.y, b.y);
    a.z = fmaxf(a.z, b.z);
    a.w = fmaxf(a.w, b.w);
    return a;
}

// One CTA per segment. 256 threads = 8 row-groups x 32 float4-columns (D=128).
// Streaming body measured at ~6.8 TB/s (~97% of the LTS path ceiling).
// Segment start computed inline with vectorized int4 reads of sizes[] so the
// pre-stream dependency chain is <=2 loads deep.
__global__ void __launch_bounds__(256, 8)
seg_prefix_max_kernel(const float* __restrict__ x,
                      const int* __restrict__ sizes,
                      const int* __restrict__ wptr,
                      float* __restrict__ out) {
    const int seg  = blockIdx.x;
    const int tid  = threadIdx.x;
    const int lane = tid & 31;
    const int wid  = tid >> 5;

    // ---- Inline exclusive-prefix: start = sum(sizes[0..seg)) ----
    // Vectorized over int4: seg4 full int4 groups + (seg & 3) scalar tail.
    const int seg4 = seg >> 2;
    const int4* __restrict__ s4 = reinterpret_cast<const int4*>(sizes);
    int psum = 0;
    for (int i = tid; i < seg4; i += 256) {
        const int4 v = s4[i];
        psum += v.x + v.y + v.z + v.w;
    }
    if (tid < (seg & 3)) psum += sizes[seg4 * 4 + tid];
    #pragma unroll
    for (int d = 16; d > 0; d >>= 1)
        psum += __shfl_down_sync(0xFFFFFFFFu, psum, d);
    __shared__ int ssum[8];
    if (lane == 0) ssum[wid] = psum;
    __syncthreads();
    const int start = ssum[0] + ssum[1] + ssum[2] + ssum[3]
                    + ssum[4] + ssum[5] + ssum[6] + ssum[7];

    const int m = sizes[seg] - wptr[0] + 1;  // rows to reduce

    const int c4   = tid & 31;   // float4 column 0..31
    const int rgrp = tid >> 5;   // row group 0..7

    const float4* __restrict__ base =
        reinterpret_cast<const float4*>(x) + (size_t)start * 32;

    float4 acc = make_float4(-CUDART_INF_F, -CUDART_INF_F,
                             -CUDART_INF_F, -CUDART_INF_F);

    // 4 independent rows in flight per thread; each warp-row is a coalesced
    // 512B load.
    int r = rgrp;
    for (; r + 24 < m; r += 32) {
        const float4 v0 = base[(r      ) * 32 + c4];
        const float4 v1 = base[(r +  8) * 32 + c4];
        const float4 v2 = base[(r + 16) * 32 + c4];
        const float4 v3 = base[(r + 24) * 32 + c4];
        acc = fmax4(acc, fmax4(fmax4(v0, v1), fmax4(v2, v3)));
    }
    for (; r < m; r += 8) {
        acc = fmax4(acc, base[r * 32 + c4]);
    }

    // Reduce the 8 row-groups down to 1 via shared memory.
    __shared__ float4 sm[256];
    sm[tid] = acc;
    __syncthreads();
    if (tid < 128) sm[tid] = fmax4(sm[tid], sm[tid + 128]);
    __syncthreads();
    if (tid < 64)  sm[tid] = fmax4(sm[tid], sm[tid + 64]);
    __syncthreads();
    if (tid < 32) {
        const float4 res = fmax4(sm[tid], sm[tid + 32]);
        reinterpret_cast<float4*>(out)[seg * 32 + c4] = res;
    }
}

extern "C" void kernel_launch(void* const* d_in, const int* in_sizes, int n_in,
                              void* d_out, int out_size) {
    const float* x     = (const float*)d_in[0];
    const int*   sizes = (const int*)d_in[1];
    const int*   wptr  = (const int*)d_in[2];
    float*       out   = (float*)d_out;

    const int n_seg = in_sizes[1];

    seg_prefix_max_kernel<<<n_seg, 256>>>(x, sizes, wptr, out);
}

// round 13
// speedup vs baseline: 1.0040x; 1.0040x over previous
#include <cuda_runtime.h>
#include <cuda_bf16.h>
#include <math_constants.h>

__device__ __forceinline__ float4 fmax4(float4 a, float4 b) {
    a.x = fmaxf(a.x, b.x);
    a.y = fmaxf(a.y, b.y);
    a.z = fmaxf(a.z, b.z);
    a.w = fmaxf(a.w, b.w);
    return a;
}

// Streaming load, evict-first: data is touched exactly once, don't fill L2.
__device__ __forceinline__ float4 ld_stream(const float4* p) {
    return __ldcs(p);
}

// One CTA per segment. 256 threads = 8 row-groups x 32 float4-columns (D=128).
// Kernel measured at 99% of the LTS-path bandwidth floor (~78.7us for 535MB).
__global__ void __launch_bounds__(256, 8)
seg_prefix_max_kernel(const float* __restrict__ x,
                      const int* __restrict__ sizes,
                      const int* __restrict__ wptr,
                      float* __restrict__ out) {
    const int seg  = blockIdx.x;
    const int tid  = threadIdx.x;
    const int lane = tid & 31;
    const int wid  = tid >> 5;

    // ---- Inline exclusive-prefix: start = sum(sizes[0..seg)) ----
    const int seg4 = seg >> 2;
    const int4* __restrict__ s4 = reinterpret_cast<const int4*>(sizes);
    int psum = 0;
    for (int i = tid; i < seg4; i += 256) {
        const int4 v = s4[i];
        psum += v.x + v.y + v.z + v.w;
    }
    if (tid < (seg & 3)) psum += sizes[seg4 * 4 + tid];
    #pragma unroll
    for (int d = 16; d > 0; d >>= 1)
        psum += __shfl_down_sync(0xFFFFFFFFu, psum, d);
    __shared__ int ssum[8];
    if (lane == 0) ssum[wid] = psum;
    __syncthreads();
    const int start = ssum[0] + ssum[1] + ssum[2] + ssum[3]
                    + ssum[4] + ssum[5] + ssum[6] + ssum[7];

    const int m = sizes[seg] - wptr[0] + 1;  // rows to reduce

    const int c4   = tid & 31;   // float4 column 0..31
    const int rgrp = tid >> 5;   // row group 0..7

    const float4* __restrict__ base =
        reinterpret_cast<const float4*>(x) + (size_t)start * 32;

    float4 acc = make_float4(-CUDART_INF_F, -CUDART_INF_F,
                             -CUDART_INF_F, -CUDART_INF_F);

    // 4 independent rows in flight per thread; each warp-row is a coalesced
    // 512B streaming load.
    int r = rgrp;
    for (; r + 24 < m; r += 32) {
        const float4 v0 = ld_stream(base + (r      ) * 32 + c4);
        const float4 v1 = ld_stream(base + (r +  8) * 32 + c4);
        const float4 v2 = ld_stream(base + (r + 16) * 32 + c4);
        const float4 v3 = ld_stream(base + (r + 24) * 32 + c4);
        acc = fmax4(acc, fmax4(fmax4(v0, v1), fmax4(v2, v3)));
    }
    for (; r < m; r += 8) {
        acc = fmax4(acc, ld_stream(base + r * 32 + c4));
    }

    // Reduce the 8 row-groups down to 1 via shared memory.
    __shared__ float4 sm[256];
    sm[tid] = acc;
    __syncthreads();
    if (tid < 128) sm[tid] = fmax4(sm[tid], sm[tid + 128]);
    __syncthreads();
    if (tid < 64)  sm[tid] = fmax4(sm[tid], sm[tid + 64]);
    __syncthreads();
    if (tid < 32) {
        const float4 res = fmax4(sm[tid], sm[tid + 32]);
        reinterpret_cast<float4*>(out)[seg * 32 + c4] = res;
    }
}

extern "C" void kernel_launch(void* const* d_in, const int* in_sizes, int n_in,
                              void* d_out, int out_size) {
    const float* x     = (const float*)d_in[0];
    const int*   sizes = (const int*)d_in[1];
    const int*   wptr  = (const int*)d_in[2];
    float*       out   = (float*)d_out;

    const int n_seg = in_sizes[1];

    seg_prefix_max_kernel<<<n_seg, 256>>>(x, sizes, wptr, out);
}

// round 15
// speedup vs baseline: 1.0104x; 1.0064x over previous
#include <cuda_runtime.h>
#include <cuda_bf16.h>
#include <math_constants.h>

__device__ __forceinline__ float4 fmax4(float4 a, float4 b) {
    a.x = fmaxf(a.x, b.x);
    a.y = fmaxf(a.y, b.y);
    a.z = fmaxf(a.z, b.z);
    a.w = fmaxf(a.w, b.w);
    return a;
}

// One CTA per segment. 256 threads = 8 row-groups x 32 float4-columns (D=128).
// Streaming body measured at ~6.8 TB/s (~99% of the LTS-path bandwidth floor
// of 78.7us for 535MB). Segment start computed inline with vectorized int4
// reads of sizes[] so the pre-stream dependency chain is <=2 loads deep.
__global__ void __launch_bounds__(256, 8)
seg_prefix_max_kernel(const float* __restrict__ x,
                      const int* __restrict__ sizes,
                      const int* __restrict__ wptr,
                      float* __restrict__ out) {
    const int seg  = blockIdx.x;
    const int tid  = threadIdx.x;
    const int lane = tid & 31;
    const int wid  = tid >> 5;

    // ---- Inline exclusive-prefix: start = sum(sizes[0..seg)) ----
    // Vectorized over int4: seg4 full int4 groups + (seg & 3) scalar tail.
    const int seg4 = seg >> 2;
    const int4* __restrict__ s4 = reinterpret_cast<const int4*>(sizes);
    int psum = 0;
    for (int i = tid; i < seg4; i += 256) {
        const int4 v = s4[i];
        psum += v.x + v.y + v.z + v.w;
    }
    if (tid < (seg & 3)) psum += sizes[seg4 * 4 + tid];
    #pragma unroll
    for (int d = 16; d > 0; d >>= 1)
        psum += __shfl_down_sync(0xFFFFFFFFu, psum, d);
    __shared__ int ssum[8];
    if (lane == 0) ssum[wid] = psum;
    __syncthreads();
    const int start = ssum[0] + ssum[1] + ssum[2] + ssum[3]
                    + ssum[4] + ssum[5] + ssum[6] + ssum[7];

    const int m = sizes[seg] - wptr[0] + 1;  // rows to reduce

    const int c4   = tid & 31;   // float4 column 0..31
    const int rgrp = tid >> 5;   // row group 0..7

    const float4* __restrict__ base =
        reinterpret_cast<const float4*>(x) + (size_t)start * 32;

    float4 acc = make_float4(-CUDART_INF_F, -CUDART_INF_F,
                             -CUDART_INF_F, -CUDART_INF_F);

    // 4 independent rows in flight per thread; each warp-row is a coalesced
    // 512B load.
    int r = rgrp;
    for (; r + 24 < m; r += 32) {
        const float4 v0 = base[(r      ) * 32 + c4];
        const float4 v1 = base[(r +  8) * 32 + c4];
        const float4 v2 = base[(r + 16) * 32 + c4];
        const float4 v3 = base[(r + 24) * 32 + c4];
        acc = fmax4(acc, fmax4(fmax4(v0, v1), fmax4(v2, v3)));
    }
    for (; r < m; r += 8) {
        acc = fmax4(acc, base[r * 32 + c4]);
    }

    // Reduce the 8 row-groups down to 1 via shared memory.
    __shared__ float4 sm[256];
    sm[tid] = acc;
    __syncthreads();
    if (tid < 128) sm[tid] = fmax4(sm[tid], sm[tid + 128]);
    __syncthreads();
    if (tid < 64)  sm[tid] = fmax4(sm[tid], sm[tid + 64]);
    __syncthreads();
    if (tid < 32) {
        const float4 res = fmax4(sm[tid], sm[tid + 32]);
        reinterpret_cast<float4*>(out)[seg * 32 + c4] = res;
    }
}

extern "C" void kernel_launch(void* const* d_in, const int* in_sizes, int n_in,
                              void* d_out, int out_size) {
    const float* x     = (const float*)d_in[0];
    const int*   sizes = (const int*)d_in[1];
    const int*   wptr  = (const int*)d_in[2];
    float*       out   = (float*)d_out;

    const int n_seg = in_sizes[1];

    seg_prefix_max_kernel<<<n_seg, 256>>>(x, sizes, wptr, out);
}